// round 8
// baseline (speedup 1.0000x reference)
#include <cuda_runtime.h>

#define B_SZ 256
#define T_SZ 2000
#define F_SZ 128

#define SLICE_T 8                       // timesteps per producer unit
#define NSLICE  (T_SZ / SLICE_T)        // 250 (exact)
#define NUNITS  (NSLICE * B_SZ)         // 64000
#define CHUNK_T 32                      // consumer chunk (timesteps)
#define NCHUNK  63                      // ceil(2000/32); last chunk = 16
#define PBLOCKS 296
#define CBLOCKS 8
#define THREADS 256
#define PWARPS  (PBLOCKS * 8)           // 2368

// BETA = sigmoid(2.0), VTH = 1.0
#define BETA_F 0.8807970779778823f

// Scratch (device globals — allocation-free). g_done is zero at load;
// consumers reset consumed cells to 0, so every graph replay starts clean.
__device__ float g_cur[T_SZ * B_SZ];        // cur, [T][B] layout
__device__ int   g_done[B_SZ * NCHUNK];     // per-(row,chunk) progress

static __device__ __forceinline__ int ld_acquire(const int* p) {
    int v;
    asm volatile("ld.acquire.gpu.global.s32 %0, [%1];"
                 : "=r"(v) : "l"(p) : "memory");
    return v;
}
static __device__ __forceinline__ void red_release_add(int* p, int v) {
    asm volatile("red.release.gpu.global.add.s32 [%0], %1;"
                 :: "l"(p), "r"(v) : "memory");
}

__global__ void __launch_bounds__(THREADS) lif_kernel(
    const float* __restrict__ x, const float* __restrict__ W,
    const float* __restrict__ bias, float* __restrict__ out, int out_size)
{
    const int wid  = threadIdx.x >> 5;
    const int lane = threadIdx.x & 31;

    if (blockIdx.x >= CBLOCKS) {
        // ===================== producers =====================
        // 8 lanes per timestep row, 4 rows per pass, 2 passes per unit.
        const int sub = lane & 7;
        const int grp = lane >> 3;

        float4 w4[4];
        #pragma unroll
        for (int j = 0; j < 4; ++j)
            w4[j] = reinterpret_cast<const float4*>(W)[sub + 8 * j];
        const float bias_v = bias[0];

        const int wg = (blockIdx.x - CBLOCKS) * 8 + wid;
        const float4* X4 = reinterpret_cast<const float4*>(x);

        for (int u = wg; u < NUNITS; u += PWARPS) {
            const int sl = u >> 8;          // slice index (time-major)
            const int b  = u & 255;         // row
            const int t0 = sl << 3;
            const float4* xp = X4 + ((size_t)b * T_SZ + t0) * (F_SZ / 4);

            // Phase 1: batch all 8 LDG.128 (4KB/warp in flight)
            float4 xv[2][4];
            #pragma unroll
            for (int p = 0; p < 2; ++p)
                #pragma unroll
                for (int j = 0; j < 4; ++j)
                    xv[p][j] = xp[(p * 4 + grp) * (F_SZ / 4) + sub + 8 * j];

            // Phase 2: dot + 3-stage 8-lane butterfly; scatter to g_cur[T][B]
            #pragma unroll
            for (int p = 0; p < 2; ++p) {
                float s = 0.0f;
                #pragma unroll
                for (int j = 0; j < 4; ++j) {
                    s = fmaf(xv[p][j].x, w4[j].x, s);
                    s = fmaf(xv[p][j].y, w4[j].y, s);
                    s = fmaf(xv[p][j].z, w4[j].z, s);
                    s = fmaf(xv[p][j].w, w4[j].w, s);
                }
                s += __shfl_xor_sync(0xFFFFFFFFu, s, 4);
                s += __shfl_xor_sync(0xFFFFFFFFu, s, 2);
                s += __shfl_xor_sync(0xFFFFFFFFu, s, 1);
                if (sub == 0)
                    g_cur[(t0 + p * 4 + grp) * B_SZ + b] = s + bias_v;
            }

            // release THIS lane's two stores: +2 per storing lane,
            // +8 per unit total = +1 per timestep → chunk target = nt
            if (sub == 0)
                red_release_add(&g_done[b * NCHUNK + (sl >> 2)], 2);
        }
    } else if (wid == 0) {
        // ===================== consumers =====================
        const int b = blockIdx.x * 32 + lane;    // row owned by this lane
        float v = 0.0f;
        float* orow = out + (size_t)b * T_SZ;

        for (int c = 0; c < NCHUNK; ++c) {
            const int tb = c * CHUNK_T;
            const int nt = (T_SZ - tb < CHUNK_T) ? (T_SZ - tb) : CHUNK_T;
            int* dp = &g_done[b * NCHUNK + c];

            while (ld_acquire(dp) < nt) { }      // all units of chunk released

            // batch-load cur (warp-coalesced, L2-resident; tail clamped)
            float cv[CHUNK_T];
            #pragma unroll
            for (int t = 0; t < CHUNK_T; ++t) {
                int tt = tb + t; tt = (tt < T_SZ) ? tt : (T_SZ - 1);
                cv[t] = g_cur[tt * B_SZ + b];
            }
            *dp = 0;                              // reset for next graph replay

            #pragma unroll
            for (int g = 0; g < CHUNK_T / 4; ++g) {
                if (tb + g * 4 >= T_SZ) break;
                float4 sp;
                #pragma unroll
                for (int k = 0; k < 4; ++k) {
                    float cu = cv[g * 4 + k];
                    float u  = fmaf(BETA_F, v, cu);   // leaky integrate
                    float um = u - 1.0f;              // off critical path
                    bool  p  = (u >= 1.0f);           // threshold (VTH=1)
                    v = p ? um : u;                   // subtraction reset
                    ((float*)&sp)[k] = p ? 1.0f : 0.0f;
                }
                reinterpret_cast<float4*>(orow + tb + g * 4)[0] = sp;
            }
        }

        // final membrane potential vT
        if (out_size > B_SZ * T_SZ)
            out[B_SZ * T_SZ + b] = v;
    }
}

extern "C" void kernel_launch(void* const* d_in, const int* in_sizes, int n_in,
                              void* d_out, int out_size)
{
    const float* x    = (const float*)d_in[0];  // [256, 2000, 128] fp32
    const float* W    = (const float*)d_in[1];  // [128, 1] fp32
    const float* bias = (const float*)d_in[2];  // [1] fp32
    float* out = (float*)d_out;                 // spikes [256*2000] then vT [256]

    lif_kernel<<<CBLOCKS + PBLOCKS, THREADS>>>(x, W, bias, out, out_size);
}

// round 9
// speedup vs baseline: 4.4204x; 4.4204x over previous
#include <cuda_runtime.h>

#define B_SZ 256
#define T_SZ 2000
#define F_SZ 128

#define CHUNK   64                 // timesteps per pipeline chunk
#define NCHUNK  32                 // ceil(2000/64); last chunk has 16 valid
#define NBUF    4                  // smem ring depth
#define DOT_WARPS 8
#define T_PER_WARP 8               // rows per dot warp per chunk
#define THREADS (32 * (DOT_WARPS + 1))  // 288: warp 0 = scan, warps 1..8 = dot

// BETA = sigmoid(2.0), VTH = 1.0
#define BETA_F 0.8807970779778823f

// named barriers: FULL(i) "buffer i produced", EMPTY(i) "buffer i free"
#define BAR_FULL(i)  (1 + (i))
#define BAR_EMPTY(i) (1 + NBUF + (i))

__device__ __forceinline__ void bar_sync(int id) {
    asm volatile("bar.sync %0, %1;" :: "r"(id), "n"(THREADS) : "memory");
}
__device__ __forceinline__ void bar_arrive(int id) {
    asm volatile("bar.arrive %0, %1;" :: "r"(id), "n"(THREADS) : "memory");
}

__global__ void __launch_bounds__(THREADS, 2) lif_fused_kernel(
    const float* __restrict__ x, const float* __restrict__ W,
    const float* __restrict__ bias, float* __restrict__ out, int out_size)
{
    __shared__ float cur_s[NBUF][CHUNK];

    const int b    = blockIdx.x;          // batch row
    const int wid  = threadIdx.x >> 5;
    const int lane = threadIdx.x & 31;

    if (wid > 0) {
        // ================= producers: dot warps 1..8 =================
        // 8 lanes per timestep-row, 4 rows per pass, 2 passes per chunk.
        const int sub = lane & 7;
        const int grp = lane >> 3;

        float4 w4[4];
        #pragma unroll
        for (int j = 0; j < 4; ++j)
            w4[j] = reinterpret_cast<const float4*>(W)[sub + 8 * j];
        const float bias_v = bias[0];

        const int slice0 = (wid - 1) * T_PER_WARP;
        const float4* X4 = reinterpret_cast<const float4*>(
            x + (size_t)b * T_SZ * F_SZ);

        // batch-load one chunk's 8 LDG.128 into dst (registers only)
        auto load_batch = [&](float4 (&dst)[2][4], int c) {
            const int t0 = c * CHUNK + slice0;
            #pragma unroll
            for (int p = 0; p < 2; ++p) {
                int trow = t0 + p * 4 + grp;
                trow = (trow < T_SZ) ? trow : (T_SZ - 1);   // clamp tail
                const float4* rp = X4 + (size_t)trow * (F_SZ / 4) + sub;
                #pragma unroll
                for (int j = 0; j < 4; ++j)
                    dst[p][j] = rp[8 * j];
            }
        };

        // reduce one chunk from src and store its cur slice to the ring
        auto reduce_store = [&](const float4 (&src)[2][4], int c) {
            const int buf = c & (NBUF - 1);
            const int t0  = c * CHUNK + slice0;
            #pragma unroll
            for (int p = 0; p < 2; ++p) {
                float s = 0.0f;
                #pragma unroll
                for (int j = 0; j < 4; ++j) {
                    s = fmaf(src[p][j].x, w4[j].x, s);
                    s = fmaf(src[p][j].y, w4[j].y, s);
                    s = fmaf(src[p][j].z, w4[j].z, s);
                    s = fmaf(src[p][j].w, w4[j].w, s);
                }
                s += __shfl_xor_sync(0xFFFFFFFFu, s, 4);
                s += __shfl_xor_sync(0xFFFFFFFFu, s, 2);
                s += __shfl_xor_sync(0xFFFFFFFFu, s, 1);
                const int trow = t0 + p * 4 + grp;
                if (sub == 0 && trow < T_SZ)
                    cur_s[buf][trow - c * CHUNK] = s + bias_v;
            }
        };

        float4 xv[2][4];   // even-chunk buffer
        float4 xn[2][4];   // odd-chunk buffer
        load_batch(xv, 0); // prologue

        #pragma unroll 1
        for (int c = 0; c < NCHUNK; c += 2) {
            // --- even chunk c: prefetch c+1, consume xv ---
            load_batch(xn, c + 1);              // in flight through reduce+scan
            bar_sync(BAR_EMPTY(c & (NBUF - 1)));
            reduce_store(xv, c);
            bar_arrive(BAR_FULL(c & (NBUF - 1)));

            // --- odd chunk c+1: prefetch c+2, consume xn ---
            const int c2 = (c + 2 < NCHUNK) ? c + 2 : NCHUNK - 1;  // clamp
            load_batch(xv, c2);
            bar_sync(BAR_EMPTY((c + 1) & (NBUF - 1)));
            reduce_store(xn, c + 1);
            bar_arrive(BAR_FULL((c + 1) & (NBUF - 1)));
        }
    } else {
        // ================= consumer: scan warp 0 =================
        #pragma unroll
        for (int i = 0; i < NBUF; ++i)
            bar_arrive(BAR_EMPTY(i));   // prime the ring

        float v = 0.0f;
        float* out_row = out + (size_t)b * T_SZ;

        for (int c = 0; c < NCHUNK; ++c) {
            const int buf = c & (NBUF - 1);

            bar_sync(BAR_FULL(buf));    // wait for all 8 producer arrivals

            if (lane == 0) {
                const int tbase = c * CHUNK;
                const int ngrp  = ((c == NCHUNK - 1) ? (T_SZ - tbase) : CHUNK) / 4;
                #pragma unroll 4
                for (int g = 0; g < ngrp; ++g) {
                    float4 cu4 = reinterpret_cast<const float4*>(
                        &cur_s[buf][g * 4])[0];
                    float4 spk4;
                    #pragma unroll
                    for (int k = 0; k < 4; ++k) {
                        float cu = ((const float*)&cu4)[k];
                        float u  = fmaf(BETA_F, v, cu);   // leaky integrate
                        float um = u - 1.0f;              // off critical path
                        bool  p  = (u >= 1.0f);           // threshold (VTH=1)
                        v = p ? um : u;                   // subtraction reset
                        ((float*)&spk4)[k] = p ? 1.0f : 0.0f;
                    }
                    reinterpret_cast<float4*>(out_row + tbase + g * 4)[0] = spk4;
                }
            }

            bar_arrive(BAR_EMPTY(buf)); // release ring slot
        }

        // final membrane potential vT
        if (lane == 0 && out_size > B_SZ * T_SZ)
            out[B_SZ * T_SZ + b] = v;
    }
}

extern "C" void kernel_launch(void* const* d_in, const int* in_sizes, int n_in,
                              void* d_out, int out_size)
{
    const float* x    = (const float*)d_in[0];  // [256, 2000, 128] fp32
    const float* W    = (const float*)d_in[1];  // [128, 1] fp32
    const float* bias = (const float*)d_in[2];  // [1] fp32
    float* out = (float*)d_out;                 // spikes [256*2000] then vT [256]

    lif_fused_kernel<<<B_SZ, THREADS>>>(x, W, bias, out, out_size);
}

// round 11
// speedup vs baseline: 4.4353x; 1.0034x over previous
#include <cuda_runtime.h>

#define B_SZ 256
#define T_SZ 2000
#define F_SZ 128

#define CHUNK   64                 // timesteps per pipeline chunk
#define NCHUNK  32                 // ceil(2000/64); last chunk has 16 valid
#define NBUF    8                  // smem ring depth
#define DOT_WARPS 8
#define T_PER_WARP 8               // rows per dot warp per chunk
#define THREADS (32 * (DOT_WARPS + 1))  // 288: warp 0 = scan, warps 1..8 = dot

// BETA = sigmoid(2.0), VTH = 1.0
#define BETA_F 0.8807970779778823f

// 16 distinct physical barriers (0..15). We never call __syncthreads(), so
// barrier 0 is ours. FULL(i)=i signals "buffer i produced"; EMPTY(i)=8+i
// signals "buffer i free". Strict 1:1 arrive/sync alternation per barrier.
#define BAR_FULL(i)  ((i) & 7)
#define BAR_EMPTY(i) (8 + ((i) & 7))

__device__ __forceinline__ void bar_sync(int id) {
    asm volatile("bar.sync %0, %1;" :: "r"(id), "n"(THREADS) : "memory");
}
__device__ __forceinline__ void bar_arrive(int id) {
    asm volatile("bar.arrive %0, %1;" :: "r"(id), "n"(THREADS) : "memory");
}

__global__ void __launch_bounds__(THREADS, 2) lif_fused_kernel(
    const float* __restrict__ x, const float* __restrict__ W,
    const float* __restrict__ bias, float* __restrict__ out, int out_size)
{
    __shared__ float cur_s[NBUF][CHUNK];

    const int b    = blockIdx.x;          // batch row
    const int wid  = threadIdx.x >> 5;
    const int lane = threadIdx.x & 31;

    if (wid > 0) {
        // ================= producers: dot warps 1..8 =================
        const int sub = lane & 7;
        const int grp = lane >> 3;

        float4 w4[4];
        #pragma unroll
        for (int j = 0; j < 4; ++j)
            w4[j] = reinterpret_cast<const float4*>(W)[sub + 8 * j];
        const float bias_v = bias[0];

        const int slice0 = (wid - 1) * T_PER_WARP;
        const float4* X4 = reinterpret_cast<const float4*>(
            x + (size_t)b * T_SZ * F_SZ);

        auto load_batch = [&](float4 (&dst)[2][4], int c) {
            const int t0 = c * CHUNK + slice0;
            #pragma unroll
            for (int p = 0; p < 2; ++p) {
                int trow = t0 + p * 4 + grp;
                trow = (trow < T_SZ) ? trow : (T_SZ - 1);   // clamp tail
                const float4* rp = X4 + (size_t)trow * (F_SZ / 4) + sub;
                #pragma unroll
                for (int j = 0; j < 4; ++j)
                    dst[p][j] = rp[8 * j];
            }
        };

        auto reduce_store = [&](const float4 (&src)[2][4], int c) {
            const int buf = c & (NBUF - 1);
            const int t0  = c * CHUNK + slice0;
            #pragma unroll
            for (int p = 0; p < 2; ++p) {
                float s = 0.0f;
                #pragma unroll
                for (int j = 0; j < 4; ++j) {
                    s = fmaf(src[p][j].x, w4[j].x, s);
                    s = fmaf(src[p][j].y, w4[j].y, s);
                    s = fmaf(src[p][j].z, w4[j].z, s);
                    s = fmaf(src[p][j].w, w4[j].w, s);
                }
                s += __shfl_xor_sync(0xFFFFFFFFu, s, 4);
                s += __shfl_xor_sync(0xFFFFFFFFu, s, 2);
                s += __shfl_xor_sync(0xFFFFFFFFu, s, 1);
                const int trow = t0 + p * 4 + grp;
                if (sub == 0 && trow < T_SZ)
                    cur_s[buf][trow - c * CHUNK] = s + bias_v;
            }
        };

        float4 xv[2][4];
        float4 xn[2][4];
        load_batch(xv, 0);

        #pragma unroll 1
        for (int c = 0; c < NCHUNK; c += 2) {
            load_batch(xn, c + 1);
            bar_sync(BAR_EMPTY(c));
            reduce_store(xv, c);
            bar_arrive(BAR_FULL(c));

            const int c2 = (c + 2 < NCHUNK) ? c + 2 : NCHUNK - 1;
            load_batch(xv, c2);
            bar_sync(BAR_EMPTY(c + 1));
            reduce_store(xn, c + 1);
            bar_arrive(BAR_FULL(c + 1));
        }
    } else {
        // ================= consumer: scan warp 0 =================
        // prime the ring: one arrive per EMPTY barrier (8 free slots)
        #pragma unroll
        for (int i = 0; i < NBUF; ++i)
            bar_arrive(BAR_EMPTY(i));

        float v = 0.0f;
        float* out_row = out + (size_t)b * T_SZ;

        for (int c = 0; c < NCHUNK; ++c) {
            bar_sync(BAR_FULL(c));      // wait for all 8 producer arrivals

            if (lane == 0) {
                const int buf   = c & (NBUF - 1);
                const int tbase = c * CHUNK;
                const int ngrp  = ((c == NCHUNK - 1) ? (T_SZ - tbase) : CHUNK) / 4;
                const float4* cs = reinterpret_cast<const float4*>(&cur_s[buf][0]);
                float* op = out_row + tbase;

                float4 cu = cs[0];                    // prefetch group 0
                #pragma unroll 4
                for (int g = 0; g < ngrp; ++g) {
                    float4 nxt;
                    if (g + 1 < ngrp) nxt = cs[g + 1];  // prefetch next group
                    float4 spk4;
                    #pragma unroll
                    for (int k = 0; k < 4; ++k) {
                        float cuv = ((const float*)&cu)[k];
                        float u   = fmaf(BETA_F, v, cuv); // leaky integrate
                        float um  = u - 1.0f;             // off critical path
                        bool  p   = (u >= 1.0f);          // threshold (VTH=1)
                        v = p ? um : u;                   // subtraction reset
                        ((float*)&spk4)[k] = p ? 1.0f : 0.0f;
                    }
                    reinterpret_cast<float4*>(op + g * 4)[0] = spk4;
                    cu = nxt;
                }
            }

            bar_arrive(BAR_EMPTY(c));   // release ring slot
        }

        // final membrane potential vT
        if (lane == 0 && out_size > B_SZ * T_SZ)
            out[B_SZ * T_SZ + b] = v;
    }
}

extern "C" void kernel_launch(void* const* d_in, const int* in_sizes, int n_in,
                              void* d_out, int out_size)
{
    const float* x    = (const float*)d_in[0];  // [256, 2000, 128] fp32
    const float* W    = (const float*)d_in[1];  // [128, 1] fp32
    const float* bias = (const float*)d_in[2];  // [1] fp32
    float* out = (float*)d_out;                 // spikes [256*2000] then vT [256]

    lif_fused_kernel<<<B_SZ, THREADS>>>(x, W, bias, out, out_size);
}